// round 12
// baseline (speedup 1.0000x reference)
#include <cuda_runtime.h>
#include <math.h>
#include <stdint.h>

// Scratch (no allocations allowed): per-block partials + completion counter.
__device__ double g_partials[512];
__device__ unsigned int g_counter = 0;

#define NBLOCKS    296       // one wave: 2 CTAs/SM * 148 SMs
#define THREADS    512
#define TILE_BYTES 32768     // 32 KB = 2048 float4
#define TILE_F4    2048
#define STAGES     2
#define SMEM_DATA  128
#define SMEM_TOTAL (SMEM_DATA + STAGES * TILE_BYTES)

// ---- PTX helpers -----------------------------------------------------------
__device__ __forceinline__ uint32_t smem_u32(const void* p) {
    return (uint32_t)__cvta_generic_to_shared(p);
}
__device__ __forceinline__ void mbar_init(uint32_t mbar, uint32_t cnt) {
    asm volatile("mbarrier.init.shared.b64 [%0], %1;" :: "r"(mbar), "r"(cnt) : "memory");
}
__device__ __forceinline__ void mbar_expect_tx(uint32_t mbar, uint32_t bytes) {
    asm volatile("mbarrier.arrive.expect_tx.shared.b64 _, [%0], %1;"
                 :: "r"(mbar), "r"(bytes) : "memory");
}
__device__ __forceinline__ void bulk_g2s(uint32_t dst, const void* src,
                                         uint32_t bytes, uint32_t mbar) {
    asm volatile("cp.async.bulk.shared::cluster.global.mbarrier::complete_tx::bytes "
                 "[%0], [%1], %2, [%3];"
                 :: "r"(dst), "l"(src), "r"(bytes), "r"(mbar) : "memory");
}
__device__ __forceinline__ void mbar_wait(uint32_t mbar, uint32_t parity) {
    asm volatile(
        "{\n\t.reg .pred P;\n\t"
        "WAIT_%=:\n\t"
        "mbarrier.try_wait.parity.acquire.cta.shared::cta.b64 P, [%0], %1, 0x989680;\n\t"
        "@!P bra WAIT_%=;\n\t"
        "}"
        :: "r"(mbar), "r"(parity) : "memory");
}
// ----------------------------------------------------------------------------

__device__ __forceinline__ float quad_eval(float4 v, float m0, float m1, float m2, float m3,
                                           float a0, float tb0, float c0,
                                           float a1, float tb1, float c1) {
    float d0 = v.x - m0, d1 = v.y - m1, d2 = v.z - m2, d3 = v.w - m3;
    float q = a0 * d0 * d0;
    q = fmaf(tb0 * d0, d1, q);
    q = fmaf(c0 * d1, d1, q);
    q = fmaf(a1 * d2, d2, q);
    q = fmaf(tb1 * d2, d3, q);
    q = fmaf(c1 * d3, d3, q);
    return q;
}

__global__ void __launch_bounds__(THREADS, 2)
fused_kernel(const float4* __restrict__ obs4,
             const float* __restrict__ mu_like,
             const float* __restrict__ pose,
             const float* __restrict__ sp,
             const float* __restrict__ sl,
             long long n4h,        // region1 float4 count (multiple of 4)
             long long n4r2,       // region2 float4 count
             long long ntiles2,    // ceil(n4r2 / TILE_F4)
             long long n,
             float* __restrict__ out) {
    extern __shared__ char smem[];
    __shared__ float s_mu[16];
    __shared__ float s_cf[24];
    __shared__ float s_logdet;
    __shared__ bool  s_is_last;
    __shared__ double s_warp[16];

    const int tid = threadIdx.x;
    const uint32_t smem_base = smem_u32(smem);

    // ---- per-block redundant setup: 8 lanes, one 2x2 block each ----
    if (tid < 8) {
        const int b = tid;
        float pxv = mu_like[2 * b], pyv = mu_like[2 * b + 1];
        float cx = pxv, cy = pyv;
        #pragma unroll
        for (int o = 4; o > 0; o >>= 1) {
            cx += __shfl_xor_sync(0xffu, cx, o, 8);
            cy += __shfl_xor_sync(0xffu, cy, o, 8);
        }
        cx *= 0.125f; cy *= 0.125f;

        float st, ct;
        sincosf(pose[2], &st, &ct);
        float mpx = ct * (pxv - cx) - st * (pyv - cy) + pose[0];
        float mpy = st * (pxv - cx) + ct * (pyv - cy) + pose[1];

        float p0 = sp[4 * b + 0], p1 = sp[4 * b + 1], p2 = sp[4 * b + 2], p3 = sp[4 * b + 3];
        float cp00 = p0 * p0 + p1 * p1 + 1e-6f;
        float cp01 = p0 * p2 + p1 * p3;
        float cp11 = p2 * p2 + p3 * p3 + 1e-6f;
        float rdp = 1.0f / (cp00 * cp11 - cp01 * cp01);
        float Pp00 =  cp11 * rdp, Pp01 = -cp01 * rdp, Pp11 = cp00 * rdp;

        float q0 = sl[4 * b + 0], q1 = sl[4 * b + 1], q2 = sl[4 * b + 2], q3 = sl[4 * b + 3];
        float cl00 = q0 * q0 + q1 * q1 + 1e-6f;
        float cl01 = q0 * q2 + q1 * q3;
        float cl11 = q2 * q2 + q3 * q3 + 1e-6f;
        float rdl = 1.0f / (cl00 * cl11 - cl01 * cl01);
        float Pl00 =  cl11 * rdl, Pl01 = -cl01 * rdl, Pl11 = cl00 * rdl;

        float Q00 = Pp00 + Pl00, Q01 = Pp01 + Pl01, Q11 = Pp11 + Pl11;
        float dq = Q00 * Q11 - Q01 * Q01;
        float ld = logf(dq);
        #pragma unroll
        for (int o = 4; o > 0; o >>= 1)
            ld += __shfl_xor_sync(0xffu, ld, o, 8);
        if (b == 0) s_logdet = ld;

        float rdq = 1.0f / dq;
        float S00 =  Q11 * rdq, S01 = -Q01 * rdq, S11 = Q00 * rdq;

        float vx = Pp00 * mpx + Pp01 * mpy + Pl00 * pxv + Pl01 * pyv;
        float vy = Pp01 * mpx + Pp11 * mpy + Pl01 * pxv + Pl11 * pyv;
        s_mu[2 * b]     = S00 * vx + S01 * vy;
        s_mu[2 * b + 1] = S01 * vx + S11 * vy;
        s_cf[3 * b + 0] = S00;
        s_cf[3 * b + 1] = S01;
        s_cf[3 * b + 2] = S11;
    }
    if (tid == 0) {
        #pragma unroll
        for (int s = 0; s < STAGES; s++) mbar_init(smem_base + 8 * s, 1);
    }
    __syncthreads();

    // per-thread quad-form constants (class = tid & 3; all strides/bases mult of 4)
    const int cls = tid & 3;
    const int blk = 2 * cls;
    const float m0 = s_mu[4 * cls + 0], m1 = s_mu[4 * cls + 1];
    const float m2 = s_mu[4 * cls + 2], m3 = s_mu[4 * cls + 3];
    const float a0 = s_cf[3 * blk + 0], tb0 = 2.0f * s_cf[3 * blk + 1], c0 = s_cf[3 * blk + 2];
    const float a1 = s_cf[3 * blk + 3], tb1 = 2.0f * s_cf[3 * blk + 4], c1 = s_cf[3 * blk + 5];

    const long long bid = blockIdx.x;
    const long long t1 = bid * THREADS + tid;
    const long long stride = (long long)NBLOCKS * THREADS;   // 151552, mult of 4

    const char* reg2 = (const char*)(obs4 + n4h);
    const long long r2_bytes = n4r2 * 16;
    const int nt = (int)((ntiles2 - bid + NBLOCKS - 1) / NBLOCKS);  // tiles for this CTA

    // prologue: fill TMA pipeline
    if (tid == 0) {
        int pro = nt < STAGES ? nt : STAGES;
        for (int j = 0; j < pro; j++) {
            long long off = (bid + (long long)j * NBLOCKS) * TILE_BYTES;
            uint32_t bytes = (uint32_t)((r2_bytes - off < TILE_BYTES) ? (r2_bytes - off)
                                                                      : TILE_BYTES);
            uint32_t mbar = smem_base + 8 * j;
            mbar_expect_tx(mbar, bytes);
            bulk_g2s(smem_base + SMEM_DATA + j * TILE_BYTES, reg2 + off, bytes, mbar);
        }
    }

    float acc0 = 0.0f, acc1 = 0.0f, acc2 = 0.0f, acc3 = 0.0f;

    // ---- main loop: per tile, overlap 4 region1 LDGs with smem tile consume ----
    for (int k = 0; k < nt; k++) {
        // region1 batch (evict-normal LDG; issues before the mbar wait)
        float4 u0, u1, u2, u3;
        bool p0v = false, p1v = false, p2v = false, p3v = false;
        {
            long long i0 = t1 + (long long)(4 * k) * stride;
            if (i0 < n4h)              { u0 = obs4[i0];              p0v = true; }
            if (i0 + stride < n4h)     { u1 = obs4[i0 + stride];     p1v = true; }
            if (i0 + 2 * stride < n4h) { u2 = obs4[i0 + 2 * stride]; p2v = true; }
            if (i0 + 3 * stride < n4h) { u3 = obs4[i0 + 3 * stride]; p3v = true; }
        }

        const int s = k & 1;
        mbar_wait(smem_base + 8 * s, (uint32_t)((k >> 1) & 1));

        const float4* tile = (const float4*)(smem + SMEM_DATA + s * TILE_BYTES);
        long long off = (bid + (long long)k * NBLOCKS) * TILE_BYTES;
        int nf4 = (int)(((r2_bytes - off < TILE_BYTES) ? (r2_bytes - off) : TILE_BYTES) >> 4);

        if (nf4 == TILE_F4) {
            float4 w0 = tile[tid];
            float4 w1 = tile[tid + THREADS];
            float4 w2 = tile[tid + 2 * THREADS];
            float4 w3 = tile[tid + 3 * THREADS];
            acc0 += quad_eval(w0, m0, m1, m2, m3, a0, tb0, c0, a1, tb1, c1);
            acc1 += quad_eval(w1, m0, m1, m2, m3, a0, tb0, c0, a1, tb1, c1);
            acc2 += quad_eval(w2, m0, m1, m2, m3, a0, tb0, c0, a1, tb1, c1);
            acc3 += quad_eval(w3, m0, m1, m2, m3, a0, tb0, c0, a1, tb1, c1);
        } else {
            for (int j = tid; j < nf4; j += THREADS)
                acc0 += quad_eval(tile[j], m0, m1, m2, m3, a0, tb0, c0, a1, tb1, c1);
        }

        if (p0v) acc0 += quad_eval(u0, m0, m1, m2, m3, a0, tb0, c0, a1, tb1, c1);
        if (p1v) acc1 += quad_eval(u1, m0, m1, m2, m3, a0, tb0, c0, a1, tb1, c1);
        if (p2v) acc2 += quad_eval(u2, m0, m1, m2, m3, a0, tb0, c0, a1, tb1, c1);
        if (p3v) acc3 += quad_eval(u3, m0, m1, m2, m3, a0, tb0, c0, a1, tb1, c1);

        __syncthreads();   // stage fully consumed

        if (tid == 0 && k + STAGES < nt) {
            long long off2 = (bid + (long long)(k + STAGES) * NBLOCKS) * TILE_BYTES;
            uint32_t bytes = (uint32_t)((r2_bytes - off2 < TILE_BYTES) ? (r2_bytes - off2)
                                                                       : TILE_BYTES);
            uint32_t mbar = smem_base + 8 * s;
            mbar_expect_tx(mbar, bytes);
            bulk_g2s(smem_base + SMEM_DATA + s * TILE_BYTES, reg2 + off2, bytes, mbar);
        }
    }

    // ---- region1 cleanup (whatever the tile loop didn't cover) ----
    for (long long i = t1 + (long long)(4 * nt) * stride; i < n4h; i += stride)
        acc0 += quad_eval(obs4[i], m0, m1, m2, m3, a0, tb0, c0, a1, tb1, c1);

    // ---- block reduction in double ----
    double dacc = (double)acc0 + (double)acc1 + (double)acc2 + (double)acc3;
    #pragma unroll
    for (int o = 16; o > 0; o >>= 1)
        dacc += __shfl_down_sync(0xffffffffu, dacc, o);

    const int lane = tid & 31, wid = tid >> 5;
    if (lane == 0) s_warp[wid] = dacc;
    __syncthreads();
    if (wid == 0) {
        double s = (lane < 16) ? s_warp[lane] : 0.0;
        #pragma unroll
        for (int o = 8; o > 0; o >>= 1)
            s += __shfl_down_sync(0xffffffffu, s, o);
        if (lane == 0) g_partials[blockIdx.x] = s;
    }

    // ---- last-block finalize ----
    if (tid == 0) {
        __threadfence();
        unsigned int c = atomicAdd(&g_counter, 1u);
        s_is_last = (c == gridDim.x - 1);
    }
    __syncthreads();
    if (s_is_last) {
        double s = 0.0;
        for (int k = tid; k < (int)gridDim.x; k += THREADS)
            s += g_partials[k];
        #pragma unroll
        for (int o = 16; o > 0; o >>= 1)
            s += __shfl_down_sync(0xffffffffu, s, o);
        if (lane == 0) s_warp[wid] = s;
        __syncthreads();
        if (wid == 0) {
            double tot = (lane < 16) ? s_warp[lane] : 0.0;
            #pragma unroll
            for (int o = 8; o > 0; o >>= 1)
                tot += __shfl_down_sync(0xffffffffu, tot, o);
            if (lane == 0) {
                double cst = (double)n * (16.0 * 1.8378770664093453 + 0.5 * (double)s_logdet);
                out[0] = (float)(cst + 0.5 * tot);
                g_counter = 0;  // reset for next graph replay
            }
        }
    }
}

extern "C" void kernel_launch(void* const* d_in, const int* in_sizes, int n_in,
                              void* d_out, int out_size) {
    const float* obs     = (const float*)d_in[0];
    const float* mu_like = (const float*)d_in[1];
    const float* pose    = (const float*)d_in[2];
    const float* sp      = (const float*)d_in[3];
    const float* sl      = (const float*)d_in[4];
    float* out = (float*)d_out;

    long long n   = (long long)in_sizes[0] / 16;
    long long n4  = n * 4;                 // total float4 units
    long long n4h = (n4 / 2) & ~3LL;       // region1 (L2-resident target), mult of 4
    long long n4r2 = n4 - n4h;             // region2 via TMA
    long long ntiles2 = (n4r2 + TILE_F4 - 1) / TILE_F4;

    cudaFuncSetAttribute(fused_kernel, cudaFuncAttributeMaxDynamicSharedMemorySize, SMEM_TOTAL);
    fused_kernel<<<NBLOCKS, THREADS, SMEM_TOTAL>>>((const float4*)obs, mu_like, pose, sp, sl,
                                                   n4h, n4r2, ntiles2, n, out);
}

// round 14
// speedup vs baseline: 1.1702x; 1.1702x over previous
#include <cuda_runtime.h>
#include <math.h>
#include <stdint.h>

// Scratch (no allocations allowed): per-block partials + completion counter.
__device__ double g_partials[1024];
__device__ unsigned int g_counter = 0;

#define NBLOCKS 592   // one full wave: 4 blocks/SM * 148 SMs

// 256-bit load with static L2 evict_last qualifier (legal form: .v4.b64).
__device__ __forceinline__ void ldg256_evict_last(const float* __restrict__ p, float* v) {
    unsigned long long r0, r1, r2, r3;
    asm volatile("ld.global.L2::evict_last.v4.b64 {%0,%1,%2,%3}, [%4];"
        : "=l"(r0), "=l"(r1), "=l"(r2), "=l"(r3) : "l"(p));
    v[0] = __uint_as_float((unsigned)(r0));        v[1] = __uint_as_float((unsigned)(r0 >> 32));
    v[2] = __uint_as_float((unsigned)(r1));        v[3] = __uint_as_float((unsigned)(r1 >> 32));
    v[4] = __uint_as_float((unsigned)(r2));        v[5] = __uint_as_float((unsigned)(r2 >> 32));
    v[6] = __uint_as_float((unsigned)(r3));        v[7] = __uint_as_float((unsigned)(r3 >> 32));
}

// Quad form over one half-row: 8 floats = 4 complete (x,y) pairs / 2x2 blocks.
__device__ __forceinline__ float quad8(const float* v, const float* m,
                                       const float* A, const float* TB, const float* C) {
    float q = 0.0f;
    #pragma unroll
    for (int j = 0; j < 4; j++) {
        float dx = v[2 * j]     - m[2 * j];
        float dy = v[2 * j + 1] - m[2 * j + 1];
        q = fmaf(A[j] * dx, dx, q);
        q = fmaf(TB[j] * dx, dy, q);
        q = fmaf(C[j] * dy, dy, q);
    }
    return q;
}

__device__ __forceinline__ float quad_eval4(float4 v, const float* m,
                                            const float* A, const float* TB, const float* C,
                                            int half) {
    // evaluate a float4 (2 blocks) using the half-row tables (half=0 -> blocks 0-1 of
    // the class's 4; half=1 -> blocks 2-3)
    int j0 = 2 * half;
    float d0 = v.x - m[2 * j0], d1 = v.y - m[2 * j0 + 1];
    float d2 = v.z - m[2 * j0 + 2], d3 = v.w - m[2 * j0 + 3];
    float q = A[j0] * d0 * d0;
    q = fmaf(TB[j0] * d0, d1, q);
    q = fmaf(C[j0] * d1, d1, q);
    q = fmaf(A[j0 + 1] * d2, d2, q);
    q = fmaf(TB[j0 + 1] * d2, d3, q);
    q = fmaf(C[j0 + 1] * d3, d3, q);
    return q;
}

__global__ void __launch_bounds__(256, 4)
fused_kernel(const float* __restrict__ obs,
             const float* __restrict__ mu_like,
             const float* __restrict__ pose,
             const float* __restrict__ sp,
             const float* __restrict__ sl,
             long long n8, long long n8p, long long n,
             float* __restrict__ out) {
    __shared__ float s_mu[16];
    __shared__ float s_cf[24];     // 8 blocks * (S00, S01, S11)
    __shared__ float s_logdet;
    __shared__ bool  s_is_last;
    __shared__ double s_warp[8];

    const int tid = threadIdx.x;

    // ---- per-block redundant setup: 8 lanes, one 2x2 block each ----
    if (tid < 8) {
        const int b = tid;
        float pxv = mu_like[2 * b], pyv = mu_like[2 * b + 1];
        float cx = pxv, cy = pyv;
        #pragma unroll
        for (int o = 4; o > 0; o >>= 1) {
            cx += __shfl_xor_sync(0xffu, cx, o, 8);
            cy += __shfl_xor_sync(0xffu, cy, o, 8);
        }
        cx *= 0.125f; cy *= 0.125f;

        float st, ct;
        sincosf(pose[2], &st, &ct);
        float mpx = ct * (pxv - cx) - st * (pyv - cy) + pose[0];
        float mpy = st * (pxv - cx) + ct * (pyv - cy) + pose[1];

        float p0 = sp[4 * b + 0], p1 = sp[4 * b + 1], p2 = sp[4 * b + 2], p3 = sp[4 * b + 3];
        float cp00 = p0 * p0 + p1 * p1 + 1e-6f;
        float cp01 = p0 * p2 + p1 * p3;
        float cp11 = p2 * p2 + p3 * p3 + 1e-6f;
        float rdp = 1.0f / (cp00 * cp11 - cp01 * cp01);
        float Pp00 =  cp11 * rdp, Pp01 = -cp01 * rdp, Pp11 = cp00 * rdp;

        float q0 = sl[4 * b + 0], q1 = sl[4 * b + 1], q2 = sl[4 * b + 2], q3 = sl[4 * b + 3];
        float cl00 = q0 * q0 + q1 * q1 + 1e-6f;
        float cl01 = q0 * q2 + q1 * q3;
        float cl11 = q2 * q2 + q3 * q3 + 1e-6f;
        float rdl = 1.0f / (cl00 * cl11 - cl01 * cl01);
        float Pl00 =  cl11 * rdl, Pl01 = -cl01 * rdl, Pl11 = cl00 * rdl;

        float Q00 = Pp00 + Pl00, Q01 = Pp01 + Pl01, Q11 = Pp11 + Pl11;
        float dq = Q00 * Q11 - Q01 * Q01;
        float ld = logf(dq);
        #pragma unroll
        for (int o = 4; o > 0; o >>= 1)
            ld += __shfl_xor_sync(0xffu, ld, o, 8);
        if (b == 0) s_logdet = ld;

        float rdq = 1.0f / dq;
        float S00 =  Q11 * rdq, S01 = -Q01 * rdq, S11 = Q00 * rdq;

        float vx = Pp00 * mpx + Pp01 * mpy + Pl00 * pxv + Pl01 * pyv;
        float vy = Pp01 * mpx + Pp11 * mpy + Pl01 * pxv + Pl11 * pyv;
        s_mu[2 * b]     = S00 * vx + S01 * vy;
        s_mu[2 * b + 1] = S01 * vx + S11 * vy;
        s_cf[3 * b + 0] = S00;
        s_cf[3 * b + 1] = S01;
        s_cf[3 * b + 2] = S11;
    }
    __syncthreads();

    // ---- per-thread constants: half-row class (8 floats = 4 blocks) ----
    const int cls = tid & 1;       // 0: blocks 0-3, 1: blocks 4-7
    float m[8], A[4], TB[4], C[4];
    #pragma unroll
    for (int j = 0; j < 8; j++) m[j] = s_mu[8 * cls + j];
    #pragma unroll
    for (int j = 0; j < 4; j++) {
        A[j]  = s_cf[12 * cls + 3 * j + 0];
        TB[j] = 2.0f * s_cf[12 * cls + 3 * j + 1];
        C[j]  = s_cf[12 * cls + 3 * j + 2];
    }

    const long long t = (long long)blockIdx.x * blockDim.x + tid;
    const long long stride = (long long)NBLOCKS * 256;  // even -> class fixed

    float acc0 = 0.0f, acc1 = 0.0f, acc2 = 0.0f, acc3 = 0.0f;

    // ---- region 1: [0, n8p) float8 units, 256-bit evict_last loads ----
    long long i = t;
    for (; i + 3 * stride < n8p; i += 4 * stride) {
        float v0[8], v1[8], v2[8], v3[8];
        ldg256_evict_last(obs + 8 * i,                v0);
        ldg256_evict_last(obs + 8 * (i + stride),     v1);
        ldg256_evict_last(obs + 8 * (i + 2 * stride), v2);
        ldg256_evict_last(obs + 8 * (i + 3 * stride), v3);
        acc0 += quad8(v0, m, A, TB, C);
        acc1 += quad8(v1, m, A, TB, C);
        acc2 += quad8(v2, m, A, TB, C);
        acc3 += quad8(v3, m, A, TB, C);
    }
    for (; i < n8p; i += stride) {
        float v[8];
        ldg256_evict_last(obs + 8 * i, v);
        acc0 += quad8(v, m, A, TB, C);
    }

    // ---- region 2: [n8p, n8) float8 units, streaming .cs float4 loads ----
    // class preserved: stride even, n8p even.
    const float4* obs4 = (const float4*)obs;
    for (; i + 3 * stride < n8; i += 4 * stride) {
        float4 w0a = __ldcs(&obs4[2 * i]);
        float4 w0b = __ldcs(&obs4[2 * i + 1]);
        float4 w1a = __ldcs(&obs4[2 * (i + stride)]);
        float4 w1b = __ldcs(&obs4[2 * (i + stride) + 1]);
        float4 w2a = __ldcs(&obs4[2 * (i + 2 * stride)]);
        float4 w2b = __ldcs(&obs4[2 * (i + 2 * stride) + 1]);
        float4 w3a = __ldcs(&obs4[2 * (i + 3 * stride)]);
        float4 w3b = __ldcs(&obs4[2 * (i + 3 * stride) + 1]);
        acc0 += quad_eval4(w0a, m, A, TB, C, 0) + quad_eval4(w0b, m, A, TB, C, 1);
        acc1 += quad_eval4(w1a, m, A, TB, C, 0) + quad_eval4(w1b, m, A, TB, C, 1);
        acc2 += quad_eval4(w2a, m, A, TB, C, 0) + quad_eval4(w2b, m, A, TB, C, 1);
        acc3 += quad_eval4(w3a, m, A, TB, C, 0) + quad_eval4(w3b, m, A, TB, C, 1);
    }
    for (; i < n8; i += stride) {
        float4 wa = __ldcs(&obs4[2 * i]);
        float4 wb = __ldcs(&obs4[2 * i + 1]);
        acc0 += quad_eval4(wa, m, A, TB, C, 0) + quad_eval4(wb, m, A, TB, C, 1);
    }

    // ---- block reduction in double ----
    double dacc = (double)acc0 + (double)acc1 + (double)acc2 + (double)acc3;
    #pragma unroll
    for (int o = 16; o > 0; o >>= 1)
        dacc += __shfl_down_sync(0xffffffffu, dacc, o);

    const int lane = tid & 31, wid = tid >> 5;
    if (lane == 0) s_warp[wid] = dacc;
    __syncthreads();
    if (wid == 0) {
        double s = (lane < 8) ? s_warp[lane] : 0.0;
        #pragma unroll
        for (int o = 4; o > 0; o >>= 1)
            s += __shfl_down_sync(0xffffffffu, s, o);
        if (lane == 0) g_partials[blockIdx.x] = s;
    }

    // ---- last-block finalize ----
    if (tid == 0) {
        __threadfence();
        unsigned int c = atomicAdd(&g_counter, 1u);
        s_is_last = (c == gridDim.x - 1);
    }
    __syncthreads();
    if (s_is_last) {
        double s = 0.0;
        for (int k = tid; k < (int)gridDim.x; k += blockDim.x)
            s += g_partials[k];
        #pragma unroll
        for (int o = 16; o > 0; o >>= 1)
            s += __shfl_down_sync(0xffffffffu, s, o);
        if (lane == 0) s_warp[wid] = s;
        __syncthreads();
        if (wid == 0) {
            double tot = (lane < 8) ? s_warp[lane] : 0.0;
            #pragma unroll
            for (int o = 4; o > 0; o >>= 1)
                tot += __shfl_down_sync(0xffffffffu, tot, o);
            if (lane == 0) {
                double cst = (double)n * (16.0 * 1.8378770664093453 + 0.5 * (double)s_logdet);
                out[0] = (float)(cst + 0.5 * tot);
                g_counter = 0;  // reset for next graph replay
            }
        }
    }
}

extern "C" void kernel_launch(void* const* d_in, const int* in_sizes, int n_in,
                              void* d_out, int out_size) {
    const float* obs     = (const float*)d_in[0];
    const float* mu_like = (const float*)d_in[1];
    const float* pose    = (const float*)d_in[2];
    const float* sp      = (const float*)d_in[3];
    const float* sl      = (const float*)d_in[4];
    float* out = (float*)d_out;

    long long n  = (long long)in_sizes[0] / 16;
    long long n8 = n * 2;                  // float8 units (32 B each)

    // Pin first 7/8 (~112 MB) with evict_last; stream last ~16 MB evict-first.
    long long n8p = ((n8 * 7) / 8) & ~1LL; // even -> class preserved

    fused_kernel<<<NBLOCKS, 256>>>(obs, mu_like, pose, sp, sl, n8, n8p, n, out);
}